// round 16
// baseline (speedup 1.0000x reference)
#include <cuda_runtime.h>

// Problem constants (fixed by reference)
#define N_TOK 16384
#define DIM   1024
#define NPATH 8
#define CAP   4096
#define TPB   256
#define NRBLK 64                    // routing blocks (= N_TOK / TPB)
#define G     4                     // rows per fill group
#define NGRP  (NPATH * CAP / G)     // 8192 groups = total grid
#define NFILL (NGRP - NRBLK)        // 8128 fill-only blocks per launch
#define NFLAG 128                   // line-spread release flags

// Scratch (allocation-free: __device__ globals). All counters are monotonic
// and never reset -> replay-safe under CUDA graph capture (fixed quanta/launch).
__device__ float    g_gate[N_TOK];
__device__ int      g_blockCount[NRBLK * NPATH];
__device__ int      g_count[NPATH];            // clamped to CAP
__device__ int      g_inv[NPATH * CAP];        // token index for (path, slot)
__device__ unsigned g_bar1;                    // routing barrier 1 (counts ready)
__device__ unsigned g_bar2;                    // routing barrier 2 (inv ready)
__device__ unsigned g_fill;                    // fill-block ticket counter
__device__ unsigned g_flag[NFLAG * 32];        // release flags, 128B apart

__device__ __forceinline__ unsigned ld_cg(const unsigned* p) {
    unsigned v;
    asm volatile("ld.global.cg.u32 %0, [%1];" : "=r"(v) : "l"(p));
    return v;
}
__device__ __forceinline__ void st_cg(unsigned* p, unsigned v) {
    asm volatile("st.global.cg.u32 [%0], %1;" :: "l"(p), "r"(v));
}

// ---------------------------------------------------------------------------
// Single fused kernel. Blocks 0..63: route + slot-assign, then release flags.
// Blocks 64..8191: wait on flag (epoch from own ticket), then fill.
// All 8192 blocks fill one G=4 row group each (group id = blockIdx.x).
// ---------------------------------------------------------------------------
__global__ void __launch_bounds__(TPB)
fused_kernel(const float* __restrict__ x,
             const float* __restrict__ scores,
             float* __restrict__ out) {
    int b    = blockIdx.x;
    int tid  = threadIdx.x;

    if (b < NRBLK) {
        // =================== ROUTING (exact R15 logic) ===================
        int warp = tid >> 5;
        int lane = tid & 31;
        int i    = b * TPB + tid;

        __shared__ int s_cnt[NRBLK][NPATH];
        __shared__ int s_hist[NPATH];
        __shared__ int s_off[NPATH];
        __shared__ int wcnt[8][NPATH];

        if (tid < NPATH) s_hist[tid] = 0;
        __syncthreads();

        // argmax (first-max wins = jnp.argmax) + block histogram
        const float4* s4 = reinterpret_cast<const float4*>(scores);
        float4 a = s4[i * 2 + 0];
        float4 c = s4[i * 2 + 1];
        float v[8] = {a.x, a.y, a.z, a.w, c.x, c.y, c.z, c.w};
        int best = 0; float bv = v[0];
#pragma unroll
        for (int k = 1; k < 8; k++)
            if (v[k] > bv) { bv = v[k]; best = k; }

        g_gate[i] = bv;
        atomicAdd(&s_hist[best], 1);
        __syncthreads();
        if (tid < NPATH) g_blockCount[b * NPATH + tid] = s_hist[tid];
        __threadfence();
        __syncthreads();

        // barrier 1: all counts visible (epoch ticket, polite poll)
        if (tid == 0) {
            unsigned t1 = atomicAdd(&g_bar1, 1u);
            unsigned target = ((t1 / NRBLK) + 1u) * NRBLK;
            while (ld_cg(&g_bar1) < target) __nanosleep(32);
        }
        __syncthreads();
        __threadfence();

        // parallel copy counts -> smem, smem scan
        if (tid < NRBLK) {
            const int4* src =
                reinterpret_cast<const int4*>(&g_blockCount[tid * NPATH]);
            int4 c0 = src[0];
            int4 c1 = src[1];
            s_cnt[tid][0] = c0.x; s_cnt[tid][1] = c0.y;
            s_cnt[tid][2] = c0.z; s_cnt[tid][3] = c0.w;
            s_cnt[tid][4] = c1.x; s_cnt[tid][5] = c1.y;
            s_cnt[tid][6] = c1.z; s_cnt[tid][7] = c1.w;
        }
        if (tid < 8 * NPATH) reinterpret_cast<int*>(wcnt)[tid] = 0;
        __syncthreads();

        if (tid < NPATH) {
            int off = 0, total = 0;
#pragma unroll 8
            for (int bb = 0; bb < NRBLK; bb++) {
                int cc = s_cnt[bb][tid];
                if (bb < b) off += cc;
                total += cc;
            }
            s_off[tid] = off;
            if (b == 0) g_count[tid] = total < CAP ? total : CAP;
        }
        __syncthreads();

        // stable intra-block rank via match_any + warp-count scan
        unsigned m     = __match_any_sync(0xffffffffu, best);
        int      wrank = __popc(m & ((1u << lane) - 1u));
        if (wrank == 0) wcnt[warp][best] = __popc(m);
        __syncthreads();

        int base = s_off[best];
#pragma unroll
        for (int w = 0; w < 8; w++)
            if (w < warp) base += wcnt[w][best];

        int slot = base + wrank;
        if (slot < CAP) g_inv[best * CAP + slot] = i;   // overflow dropped

        // barrier 2: inv/count visible; LAST arrival releases fill flags
        __syncthreads();
        if (tid == 0) {
            __threadfence();                       // release inv writes
            unsigned t2 = atomicAdd(&g_bar2, 1u);
            unsigned target = ((t2 / NRBLK) + 1u) * NRBLK;
            if ((t2 % NRBLK) == NRBLK - 1u) {      // last router: publish
                __threadfence();
#pragma unroll 4
                for (int j = 0; j < NFLAG; j++)
                    st_cg(&g_flag[j * 32], target);
            } else {
                while (ld_cg(&g_bar2) < target) __nanosleep(64);
            }
        }
        __syncthreads();
        __threadfence();                           // acquire
    } else {
        // =================== FILL-ONLY: wait for release ===================
        __shared__ unsigned s_go;
        if (tid == 0) {
            unsigned tf = atomicAdd(&g_fill, 1u);  // 8128 tickets / launch
            unsigned k  = tf / (unsigned)NFILL;    // my launch epoch
            unsigned target = (k + 1u) * NRBLK;    // g_bar2 release value
            const unsigned* fp = &g_flag[(b & (NFLAG - 1)) * 32];
            unsigned ns = 128;
            while (ld_cg(fp) < target) {
                __nanosleep(ns);
                if (ns < 2048) ns <<= 1;
            }
            s_go = 1u;
        }
        __syncthreads();
        __threadfence();                           // acquire inv/gate/count
        (void)s_go;
    }

    // ======================= FILL (all 8192 blocks) =======================
    int row0 = b * G;                 // G divides CAP: no path crossing
    int p    = row0 >> 12;
    int t    = tid;                   // float4 index within row

    int cnt = __ldg(&g_count[p]);

    bool act[G];
    int  tok[G];
#pragma unroll
    for (int j = 0; j < G; j++) {
        int row = row0 + j;
        act[j] = (row & (CAP - 1)) < cnt;
        tok[j] = act[j] ? __ldg(&g_inv[row]) : 0;
    }

    float gt[G];
#pragma unroll
    for (int j = 0; j < G; j++)
        gt[j] = act[j] ? __ldg(&g_gate[tok[j]]) : 0.0f;

    float4 vv[G];
#pragma unroll
    for (int j = 0; j < G; j++) {
        if (act[j]) {
            const float4* x4 =
                reinterpret_cast<const float4*>(x) + (size_t)tok[j] * (DIM / 4);
            float4 w = __ldg(&x4[t]);
            vv[j] = make_float4(w.x * gt[j], w.y * gt[j], w.z * gt[j], w.w * gt[j]);
        } else {
            vv[j] = make_float4(0.f, 0.f, 0.f, 0.f);
        }
    }

#pragma unroll
    for (int j = 0; j < G; j++) {
        float4* o4 = reinterpret_cast<float4*>(out) +
                     (size_t)(row0 + j) * (DIM / 4) + t;
        __stcs(o4, vv[j]);            // evict-first: keep x hot in L2
    }
}

// ---------------------------------------------------------------------------
// Launch: single kernel, single graph node.
// ---------------------------------------------------------------------------
extern "C" void kernel_launch(void* const* d_in, const int* in_sizes, int n_in,
                              void* d_out, int out_size) {
    const float* x      = (const float*)d_in[0];   // [16384, 1024]
    const float* scores = (const float*)d_in[1];   // [16384, 8]
    float*       out    = (float*)d_out;           // [8, 4096, 1024]

    fused_kernel<<<NGRP, TPB>>>(x, scores, out);
}